// round 1
// baseline (speedup 1.0000x reference)
#include <cuda_runtime.h>
#include <math.h>

// Problem constants
#define Bb 4
#define Ss 2048
#define Ee 1024
#define Hh 16
#define Dd 64
#define Mm (Bb*Ss)      // 8192 rows for projection GEMMs
#define Nn (Hh*Dd)      // 1024 cols for QKV projections

// Scratch (device globals: allocation-free, graph-capture safe)
__device__ float g_q[(size_t)Bb*Hh*Ss*Dd];
__device__ float g_k[(size_t)Bb*Hh*Ss*Dd];
__device__ float g_v[(size_t)Bb*Hh*Ss*Dd];
__device__ float g_z[(size_t)Bb*Hh*Ss*Dd];

// ---------------------------------------------------------------------------
// Kernel 1: fused QKV projection.
// GEMM: A = x [8192 x 1024], B = W[h,e,d] viewed as [1024 x 1024] (n = h*64+d)
// Output written directly in [B,H,S,Dh] layout for the attention kernel.
// 128x128 tile, BK=8, 256 threads, 8x8 accumulator per thread.
// blockIdx.z in {0,1,2} selects Q/K/V.
// ---------------------------------------------------------------------------
__global__ __launch_bounds__(256, 2)
void proj_kernel(const float* __restrict__ x,
                 const float* __restrict__ Wq, const float* __restrict__ bq,
                 const float* __restrict__ Wk, const float* __restrict__ bk,
                 const float* __restrict__ Wv, const float* __restrict__ bv)
{
    const int sel = blockIdx.z;
    const float* W    = (sel == 0) ? Wq : ((sel == 1) ? Wk : Wv);
    const float* bias = (sel == 0) ? bq : ((sel == 1) ? bk : bv);
    float* out        = (sel == 0) ? g_q : ((sel == 1) ? g_k : g_v);

    __shared__ float As[8][128];   // As[k][m] (transposed A tile)
    __shared__ float Bs[8][128];   // Bs[k][n]

    const int t  = threadIdx.x;
    const int m0 = blockIdx.y * 128;
    const int n0 = blockIdx.x * 128;

    // A-tile load mapping: 128 rows x 8 k, two float4 per row
    const int ar = t >> 1, aq = t & 1;
    // B-tile load mapping: 8 k-rows x 128 n, one float4 per thread
    const int bkk = t >> 5, bn = (t & 31) * 4;
    // Compute mapping: 8x8 micro-tile
    const int rowg = (t >> 4) * 8, colg = (t & 15) * 8;

    const float* xptr = x + (size_t)(m0 + ar) * Ee + aq * 4;
    const int nb = n0 + bn;
    const float* wptr = W + (size_t)(nb >> 6) * (Ee * Dd) + (size_t)bkk * Dd + (nb & 63);

    float acc[8][8];
    #pragma unroll
    for (int i = 0; i < 8; i++)
        #pragma unroll
        for (int j = 0; j < 8; j++) acc[i][j] = 0.f;

    for (int k0 = 0; k0 < Ee; k0 += 8) {
        float4 av  = *(const float4*)(xptr + k0);
        float4 bv4 = *(const float4*)(wptr + (size_t)k0 * Dd);
        __syncthreads();
        As[aq*4+0][ar] = av.x;
        As[aq*4+1][ar] = av.y;
        As[aq*4+2][ar] = av.z;
        As[aq*4+3][ar] = av.w;
        *(float4*)&Bs[bkk][bn] = bv4;
        __syncthreads();
        #pragma unroll
        for (int kk = 0; kk < 8; kk++) {
            float4 a0 = *(const float4*)&As[kk][rowg];
            float4 a1 = *(const float4*)&As[kk][rowg + 4];
            float4 b0 = *(const float4*)&Bs[kk][colg];
            float4 b1 = *(const float4*)&Bs[kk][colg + 4];
            float a[8]  = {a0.x, a0.y, a0.z, a0.w, a1.x, a1.y, a1.z, a1.w};
            float bb[8] = {b0.x, b0.y, b0.z, b0.w, b1.x, b1.y, b1.z, b1.w};
            #pragma unroll
            for (int i = 0; i < 8; i++)
                #pragma unroll
                for (int j = 0; j < 8; j++)
                    acc[i][j] = fmaf(a[i], bb[j], acc[i][j]);
        }
    }

    // Epilogue: add bias, write in [B,H,S,Dh] layout
    #pragma unroll
    for (int i = 0; i < 8; i++) {
        const int m = m0 + rowg + i;
        const int bidx = m >> 11;      // / 2048
        const int s    = m & 2047;
        #pragma unroll
        for (int j = 0; j < 8; j += 4) {
            const int n = n0 + colg + j;
            const int h = n >> 6, d = n & 63;
            float4 r;
            r.x = acc[i][j+0] + bias[n+0];
            r.y = acc[i][j+1] + bias[n+1];
            r.z = acc[i][j+2] + bias[n+2];
            r.w = acc[i][j+3] + bias[n+3];
            *(float4*)&out[(size_t)(((bidx*Hh + h)*Ss) + s)*Dd + d] = r;
        }
    }
}

// ---------------------------------------------------------------------------
// Kernel 2: flash attention. One block handles 64 query rows of one (b,h).
// 256 threads as 16x16; each thread owns a 4x4 micro-tile.
// Online softmax; scores never hit HBM.
// ---------------------------------------------------------------------------
#define AT_PAD 68
#define ATTN_SMEM (4 * 64 * AT_PAD * (int)sizeof(float))   // 69632 B

__global__ __launch_bounds__(256)
void attn_kernel()
{
    extern __shared__ float smdyn[];
    float* Qt = smdyn;                 // Qt[d][r]  (Dh x 64, transposed)
    float* Kt = Qt + 64 * AT_PAD;      // Kt[d][c]
    float* Vs = Kt + 64 * AT_PAD;      // Vs[t][d]
    float* Ps = Vs + 64 * AT_PAD;      // Ps[r][t]

    const int t  = threadIdx.x;
    const int tx = t & 15, ty = t >> 4;
    const int bh = blockIdx.y;
    const int row0 = blockIdx.x * 64;
    const size_t base = (size_t)bh * Ss * Dd;

    // Load Q tile transposed
    for (int i = t; i < 64 * 16; i += 256) {
        const int r = i >> 4, c4 = (i & 15) * 4;
        float4 v = *(const float4*)&g_q[base + (size_t)(row0 + r) * Dd + c4];
        Qt[(c4+0)*AT_PAD + r] = v.x;
        Qt[(c4+1)*AT_PAD + r] = v.y;
        Qt[(c4+2)*AT_PAD + r] = v.z;
        Qt[(c4+3)*AT_PAD + r] = v.w;
    }

    float mrow[4], lrow[4], o[4][4];
    #pragma unroll
    for (int i = 0; i < 4; i++) { mrow[i] = -3.0e38f; lrow[i] = 0.f; }
    #pragma unroll
    for (int i = 0; i < 4; i++)
        #pragma unroll
        for (int j = 0; j < 4; j++) o[i][j] = 0.f;

    for (int t0 = 0; t0 < Ss; t0 += 64) {
        __syncthreads();   // previous iteration done with Kt/Vs/Ps
        for (int i = t; i < 64 * 16; i += 256) {
            const int r = i >> 4, c4 = (i & 15) * 4;
            float4 kv = *(const float4*)&g_k[base + (size_t)(t0 + r) * Dd + c4];
            Kt[(c4+0)*AT_PAD + r] = kv.x;
            Kt[(c4+1)*AT_PAD + r] = kv.y;
            Kt[(c4+2)*AT_PAD + r] = kv.z;
            Kt[(c4+3)*AT_PAD + r] = kv.w;
            float4 vv = *(const float4*)&g_v[base + (size_t)(t0 + r) * Dd + c4];
            *(float4*)&Vs[r*AT_PAD + c4] = vv;
        }
        __syncthreads();

        // S = Q K^T (4x4 per thread)
        float sacc[4][4];
        #pragma unroll
        for (int i = 0; i < 4; i++)
            #pragma unroll
            for (int j = 0; j < 4; j++) sacc[i][j] = 0.f;
        #pragma unroll
        for (int d = 0; d < 64; d++) {
            float4 qv = *(const float4*)&Qt[d*AT_PAD + ty*4];
            float4 kv = *(const float4*)&Kt[d*AT_PAD + tx*4];
            float qa[4] = {qv.x, qv.y, qv.z, qv.w};
            float ka[4] = {kv.x, kv.y, kv.z, kv.w};
            #pragma unroll
            for (int i = 0; i < 4; i++)
                #pragma unroll
                for (int j = 0; j < 4; j++)
                    sacc[i][j] = fmaf(qa[i], ka[j], sacc[i][j]);
        }

        // Online softmax per row (rows r = ty*4+ry, reduce across tx lanes)
        #pragma unroll
        for (int ry = 0; ry < 4; ry++) {
            float s0 = sacc[ry][0] * 0.125f;
            float s1 = sacc[ry][1] * 0.125f;
            float s2 = sacc[ry][2] * 0.125f;
            float s3 = sacc[ry][3] * 0.125f;
            float rmax = fmaxf(fmaxf(s0, s1), fmaxf(s2, s3));
            #pragma unroll
            for (int off = 1; off < 16; off <<= 1)
                rmax = fmaxf(rmax, __shfl_xor_sync(0xffffffffu, rmax, off));
            const float mnew = fmaxf(mrow[ry], rmax);
            const float p0 = __expf(s0 - mnew);
            const float p1 = __expf(s1 - mnew);
            const float p2 = __expf(s2 - mnew);
            const float p3 = __expf(s3 - mnew);
            float psum = (p0 + p1) + (p2 + p3);
            #pragma unroll
            for (int off = 1; off < 16; off <<= 1)
                psum += __shfl_xor_sync(0xffffffffu, psum, off);
            const float corr = __expf(mrow[ry] - mnew);
            mrow[ry] = mnew;
            lrow[ry] = lrow[ry] * corr + psum;
            #pragma unroll
            for (int j = 0; j < 4; j++) o[ry][j] *= corr;
            const int r = ty*4 + ry;
            Ps[r*AT_PAD + tx*4 + 0] = p0;
            Ps[r*AT_PAD + tx*4 + 1] = p1;
            Ps[r*AT_PAD + tx*4 + 2] = p2;
            Ps[r*AT_PAD + tx*4 + 3] = p3;
        }
        __syncthreads();

        // O += P V (4x4 per thread)
        #pragma unroll 8
        for (int tt = 0; tt < 64; tt++) {
            float pr[4];
            #pragma unroll
            for (int ry = 0; ry < 4; ry++)
                pr[ry] = Ps[(ty*4 + ry)*AT_PAD + tt];
            float4 vv = *(const float4*)&Vs[tt*AT_PAD + tx*4];
            float va[4] = {vv.x, vv.y, vv.z, vv.w};
            #pragma unroll
            for (int ry = 0; ry < 4; ry++)
                #pragma unroll
                for (int rx = 0; rx < 4; rx++)
                    o[ry][rx] = fmaf(pr[ry], va[rx], o[ry][rx]);
        }
    }

    // Normalize and write z in [B,H,S,Dh] layout
    #pragma unroll
    for (int ry = 0; ry < 4; ry++) {
        const float inv = 1.0f / lrow[ry];
        float4 r;
        r.x = o[ry][0] * inv;
        r.y = o[ry][1] * inv;
        r.z = o[ry][2] * inv;
        r.w = o[ry][3] * inv;
        *(float4*)&g_z[base + (size_t)(row0 + ty*4 + ry) * Dd + tx*4] = r;
    }
}

// ---------------------------------------------------------------------------
// Kernel 3: output projection. out[b,s,e] = z_concat[b,s,:] @ Wo + bo
// A gathered from g_z ([B,H,S,Dh] -> concat index n = h*64+d).
// ---------------------------------------------------------------------------
__global__ __launch_bounds__(256, 2)
void outproj_kernel(const float* __restrict__ Wo, const float* __restrict__ bo,
                    float* __restrict__ out)
{
    __shared__ float As[8][128];
    __shared__ float Bs[8][128];

    const int t  = threadIdx.x;
    const int m0 = blockIdx.y * 128;
    const int e0 = blockIdx.x * 128;

    const int ar = t >> 1, aq = t & 1;
    const int bkk = t >> 5, be = (t & 31) * 4;
    const int rowg = (t >> 4) * 8, colg = (t & 15) * 8;

    const int m = m0 + ar;
    const int bidx = m >> 11;
    const int s    = m & 2047;
    const float* zbase = g_z + ((size_t)bidx * Hh * Ss + s) * Dd;

    float acc[8][8];
    #pragma unroll
    for (int i = 0; i < 8; i++)
        #pragma unroll
        for (int j = 0; j < 8; j++) acc[i][j] = 0.f;

    for (int k0 = 0; k0 < Nn; k0 += 8) {
        const int n = k0 + aq * 4;
        const int h = n >> 6, d = n & 63;
        float4 av  = *(const float4*)(zbase + (size_t)h * Ss * Dd + d);
        float4 bv4 = *(const float4*)(Wo + (size_t)(k0 + bkk) * Ee + e0 + be);
        __syncthreads();
        As[aq*4+0][ar] = av.x;
        As[aq*4+1][ar] = av.y;
        As[aq*4+2][ar] = av.z;
        As[aq*4+3][ar] = av.w;
        *(float4*)&Bs[bkk][be] = bv4;
        __syncthreads();
        #pragma unroll
        for (int kk = 0; kk < 8; kk++) {
            float4 a0 = *(const float4*)&As[kk][rowg];
            float4 a1 = *(const float4*)&As[kk][rowg + 4];
            float4 b0 = *(const float4*)&Bs[kk][colg];
            float4 b1 = *(const float4*)&Bs[kk][colg + 4];
            float a[8]  = {a0.x, a0.y, a0.z, a0.w, a1.x, a1.y, a1.z, a1.w};
            float bb[8] = {b0.x, b0.y, b0.z, b0.w, b1.x, b1.y, b1.z, b1.w};
            #pragma unroll
            for (int i = 0; i < 8; i++)
                #pragma unroll
                for (int j = 0; j < 8; j++)
                    acc[i][j] = fmaf(a[i], bb[j], acc[i][j]);
        }
    }

    #pragma unroll
    for (int i = 0; i < 8; i++) {
        const int mm = m0 + rowg + i;
        #pragma unroll
        for (int j = 0; j < 8; j += 4) {
            const int e = e0 + colg + j;
            float4 r;
            r.x = acc[i][j+0] + bo[e+0];
            r.y = acc[i][j+1] + bo[e+1];
            r.z = acc[i][j+2] + bo[e+2];
            r.w = acc[i][j+3] + bo[e+3];
            *(float4*)&out[(size_t)mm * Ee + e] = r;
        }
    }
}

// ---------------------------------------------------------------------------
extern "C" void kernel_launch(void* const* d_in, const int* in_sizes, int n_in,
                              void* d_out, int out_size)
{
    const float* x  = (const float*)d_in[0];
    const float* Wq = (const float*)d_in[1];
    const float* bq = (const float*)d_in[2];
    const float* Wk = (const float*)d_in[3];
    const float* bk = (const float*)d_in[4];
    const float* Wv = (const float*)d_in[5];
    const float* bv = (const float*)d_in[6];
    const float* Wo = (const float*)d_in[7];
    const float* bo = (const float*)d_in[8];
    float* out = (float*)d_out;

    cudaFuncSetAttribute(attn_kernel,
                         cudaFuncAttributeMaxDynamicSharedMemorySize, ATTN_SMEM);

    // QKV projections (z-dim selects Q/K/V)
    proj_kernel<<<dim3(Nn/128, Mm/128, 3), 256>>>(x, Wq, bq, Wk, bk, Wv, bv);
    // Flash attention: 32 row-tiles x 64 (b,h) pairs
    attn_kernel<<<dim3(Ss/64, Bb*Hh), 256, ATTN_SMEM>>>();
    // Output projection
    outproj_kernel<<<dim3(Ee/128, Mm/128), 256>>>(Wo, bo, out);
}

// round 3
// speedup vs baseline: 2.3068x; 2.3068x over previous
#include <cuda_runtime.h>
#include <cstdint>
#include <math.h>

// Problem constants
#define Bb 4
#define Ss 2048
#define Ee 1024
#define Hh 16
#define Dd 64
#define Mm (Bb*Ss)      // 8192
#define Nn (Hh*Dd)      // 1024

// Scratch (device globals: allocation-free, graph-capture safe)
__device__ float g_q[(size_t)Bb*Hh*Ss*Dd];
__device__ float g_k[(size_t)Bb*Hh*Ss*Dd];
__device__ float g_v[(size_t)Bb*Hh*Ss*Dd];
__device__ float g_z[(size_t)Bb*Hh*Ss*Dd];

// ---------------------------------------------------------------------------
// Helpers
// ---------------------------------------------------------------------------
__device__ __forceinline__ float tf32r(float x) {
    float y; asm("cvt.rna.tf32.f32 %0, %1;" : "=f"(y) : "f"(x)); return y;
}
__device__ __forceinline__ float4 cvt4(float4 v) {
    v.x = tf32r(v.x); v.y = tf32r(v.y); v.z = tf32r(v.z); v.w = tf32r(v.w);
    return v;
}
// D += A(16x8,row) * B(8x8,col) in tf32, fp32 accumulate
__device__ __forceinline__ void mma_tf32(float* d, const uint32_t* a,
                                         const uint32_t* b) {
    asm volatile(
        "mma.sync.aligned.m16n8k8.row.col.f32.tf32.tf32.f32 "
        "{%0,%1,%2,%3}, {%4,%5,%6,%7}, {%8,%9}, {%0,%1,%2,%3};"
        : "+f"(d[0]), "+f"(d[1]), "+f"(d[2]), "+f"(d[3])
        : "r"(a[0]), "r"(a[1]), "r"(a[2]), "r"(a[3]), "r"(b[0]), "r"(b[1]));
}

// ---------------------------------------------------------------------------
// GEMM config: 128x128 block tile, K-chunk 32, 8 warps (warp tile 64x32),
// double-buffered SMEM, pitch 36 floats (conflict-free frag loads: 4g+c).
// ---------------------------------------------------------------------------
#define KC 32
#define PITCH 36
#define ABUF (128*PITCH)                 // floats per A (or B) tile
#define BUFSZ (2*ABUF)                   // A+B per buffer
#define GEMM_SMEM (2*BUFSZ*4)            // 73728 bytes

// ---------------------------------------------------------------------------
// Kernel 1: QKV projection.  D[m][n] = sum_e x[m][e] * W[h][e][d],  n=h*64+d
// Output in [B,H,S,Dh] layout with bias. blockIdx.z selects Q/K/V.
// ---------------------------------------------------------------------------
__global__ __launch_bounds__(256)
void proj_mma(const float* __restrict__ x,
              const float* __restrict__ Wq, const float* __restrict__ bq,
              const float* __restrict__ Wk, const float* __restrict__ bk,
              const float* __restrict__ Wv, const float* __restrict__ bv)
{
    extern __shared__ float sm[];
    const int sel = blockIdx.z;
    const float* W    = sel == 0 ? Wq : (sel == 1 ? Wk : Wv);
    const float* bias = sel == 0 ? bq : (sel == 1 ? bk : bv);
    float* out        = sel == 0 ? g_q : (sel == 1 ? g_k : g_v);

    const int t = threadIdx.x, lane = t & 31, wid = t >> 5;
    const int q = lane & 3, g = lane >> 2;
    const int wm = (wid & 1) * 64, wn = (wid >> 1) * 32;
    const int n0 = blockIdx.x * 128, m0 = blockIdx.y * 128;

    // load mappings
    const int am = t >> 1, ak4 = (t & 1) * 16;        // unused alt
    const int lm = t >> 3, lk4 = (t & 7) * 4;          // A: row lm, k lk4 (+256j -> +32 rows)
    const int n4 = 0;                                   // per-j below

    float acc[4][4][4];
    #pragma unroll
    for (int i = 0; i < 4; i++)
        #pragma unroll
        for (int j = 0; j < 4; j++)
            #pragma unroll
            for (int kk = 0; kk < 4; kk++) acc[i][j][kk] = 0.f;

    float4 aR[4], bR[4];

    auto load_regs = [&](int k0) {
        #pragma unroll
        for (int j = 0; j < 4; j++) {
            const int idx = t + 256 * j;
            const int m = idx >> 3, k4 = (idx & 7) * 4;
            aR[j] = *(const float4*)(x + (size_t)(m0 + m) * Ee + k0 + k4);
            const int nn4 = idx >> 5, kk = idx & 31;
            const int nrel = 4 * nn4;
            bR[j] = *(const float4*)(W + (size_t)((n0 + nrel) >> 6) * (Ee * Dd)
                                       + (size_t)(k0 + kk) * Dd + (nrel & 63));
        }
    };
    auto store_smem = [&](int buf) {
        float* A = sm + buf * BUFSZ;
        float* B = A + ABUF;
        #pragma unroll
        for (int j = 0; j < 4; j++) {
            const int idx = t + 256 * j;
            const int m = idx >> 3, k4 = (idx & 7) * 4;
            *(float4*)(A + m * PITCH + k4) = cvt4(aR[j]);
            const int nn4 = idx >> 5, kk = idx & 31;
            float4 v = cvt4(bR[j]);
            B[(4*nn4+0) * PITCH + kk] = v.x;
            B[(4*nn4+1) * PITCH + kk] = v.y;
            B[(4*nn4+2) * PITCH + kk] = v.z;
            B[(4*nn4+3) * PITCH + kk] = v.w;
        }
    };
    auto compute = [&](int buf) {
        const uint32_t* A = (const uint32_t*)(sm + buf * BUFSZ);
        const uint32_t* B = A + ABUF;
        #pragma unroll
        for (int ks = 0; ks < 4; ks++) {
            const int ko = ks * 8;
            uint32_t af[4][4];
            #pragma unroll
            for (int mt = 0; mt < 4; mt++) {
                const int r = wm + mt * 16 + g;
                af[mt][0] = A[r * PITCH + ko + q];
                af[mt][1] = A[(r + 8) * PITCH + ko + q];
                af[mt][2] = A[r * PITCH + ko + q + 4];
                af[mt][3] = A[(r + 8) * PITCH + ko + q + 4];
            }
            #pragma unroll
            for (int nt = 0; nt < 4; nt++) {
                const int n = wn + nt * 8 + g;
                uint32_t bf[2];
                bf[0] = B[n * PITCH + ko + q];
                bf[1] = B[n * PITCH + ko + q + 4];
                #pragma unroll
                for (int mt = 0; mt < 4; mt++)
                    mma_tf32(acc[mt][nt], af[mt], bf);
            }
        }
    };

    load_regs(0);
    store_smem(0);
    __syncthreads();
    const int NC = Ee / KC;
    for (int c = 0; c < NC; c++) {
        if (c + 1 < NC) load_regs((c + 1) * KC);
        compute(c & 1);
        if (c + 1 < NC) store_smem((c + 1) & 1);
        __syncthreads();
    }

    // Epilogue: bias + write [B,H,S,Dh]
    #pragma unroll
    for (int mt = 0; mt < 4; mt++) {
        #pragma unroll
        for (int rr = 0; rr < 2; rr++) {
            const int r_g = m0 + wm + mt * 16 + g + rr * 8;
            const int bi = r_g >> 11, s = r_g & 2047;
            #pragma unroll
            for (int nt = 0; nt < 4; nt++) {
                const int n_g = n0 + wn + nt * 8 + 2 * q;
                const int h = n_g >> 6, d = n_g & 63;
                float2 v;
                v.x = acc[mt][nt][2*rr + 0] + bias[n_g];
                v.y = acc[mt][nt][2*rr + 1] + bias[n_g + 1];
                *(float2*)(out + ((size_t)(bi * Hh + h) * Ss + s) * Dd + d) = v;
            }
        }
    }
}

// ---------------------------------------------------------------------------
// Kernel 3: output projection.  out[m][e] = sum_k z_c[m][k] * Wo[k][e] + bo
// A gathered from g_z ([B,H,S,Dh], k = h*64+d; K-chunk 32 stays in one head).
// ---------------------------------------------------------------------------
__global__ __launch_bounds__(256)
void outproj_mma(const float* __restrict__ Wo, const float* __restrict__ bo,
                 float* __restrict__ outp)
{
    extern __shared__ float sm[];
    const int t = threadIdx.x, lane = t & 31, wid = t >> 5;
    const int q = lane & 3, g = lane >> 2;
    const int wm = (wid & 1) * 64, wn = (wid >> 1) * 32;
    const int e0 = blockIdx.x * 128, m0 = blockIdx.y * 128;

    float acc[4][4][4];
    #pragma unroll
    for (int i = 0; i < 4; i++)
        #pragma unroll
        for (int j = 0; j < 4; j++)
            #pragma unroll
            for (int kk = 0; kk < 4; kk++) acc[i][j][kk] = 0.f;

    float4 aR[4], bR[4];

    auto load_regs = [&](int k0) {
        const int h = k0 >> 6, d0 = k0 & 63;
        #pragma unroll
        for (int j = 0; j < 4; j++) {
            const int idx = t + 256 * j;
            const int m = idx >> 3, k4 = (idx & 7) * 4;
            const int mg = m0 + m, bi = mg >> 11, s = mg & 2047;
            aR[j] = *(const float4*)(g_z + ((size_t)(bi * Hh + h) * Ss + s) * Dd
                                         + d0 + k4);
            const int nn4 = idx >> 5, kk = idx & 31;
            bR[j] = *(const float4*)(Wo + (size_t)(k0 + kk) * Ee + e0 + 4 * nn4);
        }
    };
    auto store_smem = [&](int buf) {
        float* A = sm + buf * BUFSZ;
        float* B = A + ABUF;
        #pragma unroll
        for (int j = 0; j < 4; j++) {
            const int idx = t + 256 * j;
            const int m = idx >> 3, k4 = (idx & 7) * 4;
            *(float4*)(A + m * PITCH + k4) = cvt4(aR[j]);
            const int nn4 = idx >> 5, kk = idx & 31;
            float4 v = cvt4(bR[j]);
            B[(4*nn4+0) * PITCH + kk] = v.x;
            B[(4*nn4+1) * PITCH + kk] = v.y;
            B[(4*nn4+2) * PITCH + kk] = v.z;
            B[(4*nn4+3) * PITCH + kk] = v.w;
        }
    };
    auto compute = [&](int buf) {
        const uint32_t* A = (const uint32_t*)(sm + buf * BUFSZ);
        const uint32_t* B = A + ABUF;
        #pragma unroll
        for (int ks = 0; ks < 4; ks++) {
            const int ko = ks * 8;
            uint32_t af[4][4];
            #pragma unroll
            for (int mt = 0; mt < 4; mt++) {
                const int r = wm + mt * 16 + g;
                af[mt][0] = A[r * PITCH + ko + q];
                af[mt][1] = A[(r + 8) * PITCH + ko + q];
                af[mt][2] = A[r * PITCH + ko + q + 4];
                af[mt][3] = A[(r + 8) * PITCH + ko + q + 4];
            }
            #pragma unroll
            for (int nt = 0; nt < 4; nt++) {
                const int n = wn + nt * 8 + g;
                uint32_t bf[2];
                bf[0] = B[n * PITCH + ko + q];
                bf[1] = B[n * PITCH + ko + q + 4];
                #pragma unroll
                for (int mt = 0; mt < 4; mt++)
                    mma_tf32(acc[mt][nt], af[mt], bf);
            }
        }
    };

    load_regs(0);
    store_smem(0);
    __syncthreads();
    const int NC = Nn / KC;
    for (int c = 0; c < NC; c++) {
        if (c + 1 < NC) load_regs((c + 1) * KC);
        compute(c & 1);
        if (c + 1 < NC) store_smem((c + 1) & 1);
        __syncthreads();
    }

    #pragma unroll
    for (int mt = 0; mt < 4; mt++) {
        #pragma unroll
        for (int rr = 0; rr < 2; rr++) {
            const int r_g = m0 + wm + mt * 16 + g + rr * 8;
            #pragma unroll
            for (int nt = 0; nt < 4; nt++) {
                const int e = e0 + wn + nt * 8 + 2 * q;
                float2 v;
                v.x = acc[mt][nt][2*rr + 0] + bo[e];
                v.y = acc[mt][nt][2*rr + 1] + bo[e + 1];
                *(float2*)(outp + (size_t)r_g * Ee + e) = v;
            }
        }
    }
}

// ---------------------------------------------------------------------------
// Kernel 2: flash attention with tf32 mma.
// Block: 128 threads (4 warps), 64 q-rows, loop over 64-key tiles.
// Warp w owns rows w*16..w*16+15. S and O via m16n8k8 tf32 mma.
// ---------------------------------------------------------------------------
#define APITCH 68
#define ATTN_SMEM (4 * 64 * APITCH * 4)    // Qs,Ks,Vs,Ps = 69632 B

__global__ __launch_bounds__(128)
void attn_mma()
{
    extern __shared__ float sm[];
    float* Qs = sm;
    float* Ks = Qs + 64 * APITCH;
    float* Vs = Ks + 64 * APITCH;
    float* Ps = Vs + 64 * APITCH;
    const uint32_t* Qu = (const uint32_t*)Qs;
    const uint32_t* Ku = (const uint32_t*)Ks;
    const uint32_t* Vu = (const uint32_t*)Vs;
    const uint32_t* Pu = (const uint32_t*)Ps;

    const int t = threadIdx.x, lane = t & 31, wid = t >> 5;
    const int q = lane & 3, g = lane >> 2;
    const int bh = blockIdx.y;
    const int row0 = blockIdx.x * 64;
    const size_t base = (size_t)bh * Ss * Dd;
    const int r0 = wid * 16 + g;       // thread's row (and r0+8)

    // Load Q tile (tf32)
    #pragma unroll
    for (int j = 0; j < 8; j++) {
        const int idx = t + 128 * j;
        const int r = idx >> 4, c4 = (idx & 15) * 4;
        float4 v = *(const float4*)(g_q + base + (size_t)(row0 + r) * Dd + c4);
        *(float4*)(Qs + r * APITCH + c4) = cvt4(v);
    }

    float m0r = -3.0e38f, m1r = -3.0e38f, l0r = 0.f, l1r = 0.f;
    float o[8][4];
    #pragma unroll
    for (int i = 0; i < 8; i++)
        #pragma unroll
        for (int j = 0; j < 4; j++) o[i][j] = 0.f;

    for (int t0 = 0; t0 < Ss; t0 += 64) {
        __syncthreads();
        #pragma unroll
        for (int j = 0; j < 8; j++) {
            const int idx = t + 128 * j;
            const int r = idx >> 4, c4 = (idx & 15) * 4;
            float4 kv = *(const float4*)(g_k + base + (size_t)(t0 + r) * Dd + c4);
            *(float4*)(Ks + r * APITCH + c4) = cvt4(kv);
            float4 vv = *(const float4*)(g_v + base + (size_t)(t0 + r) * Dd + c4);
            *(float4*)(Vs + r * APITCH + c4) = cvt4(vv);
        }
        __syncthreads();

        // S = Q K^T
        float s[8][4];
        #pragma unroll
        for (int i = 0; i < 8; i++)
            #pragma unroll
            for (int j = 0; j < 4; j++) s[i][j] = 0.f;
        #pragma unroll
        for (int ks = 0; ks < 8; ks++) {
            const int ko = ks * 8;
            uint32_t af[4];
            af[0] = Qu[r0 * APITCH + ko + q];
            af[1] = Qu[(r0 + 8) * APITCH + ko + q];
            af[2] = Qu[r0 * APITCH + ko + q + 4];
            af[3] = Qu[(r0 + 8) * APITCH + ko + q + 4];
            #pragma unroll
            for (int nt = 0; nt < 8; nt++) {
                const int n = nt * 8 + g;
                uint32_t bf[2];
                bf[0] = Ku[n * APITCH + ko + q];
                bf[1] = Ku[n * APITCH + ko + q + 4];
                mma_tf32(s[nt], af, bf);
            }
        }

        // Online softmax. Row r0 owns s[nt][0..1]; row r0+8 owns s[nt][2..3].
        float rmax0 = -3.0e38f, rmax1 = -3.0e38f;
        #pragma unroll
        for (int nt = 0; nt < 8; nt++) {
            #pragma unroll
            for (int j = 0; j < 4; j++) s[nt][j] *= 0.125f;
            rmax0 = fmaxf(rmax0, fmaxf(s[nt][0], s[nt][1]));
            rmax1 = fmaxf(rmax1, fmaxf(s[nt][2], s[nt][3]));
        }
        rmax0 = fmaxf(rmax0, __shfl_xor_sync(0xffffffffu, rmax0, 1));
        rmax0 = fmaxf(rmax0, __shfl_xor_sync(0xffffffffu, rmax0, 2));
        rmax1 = fmaxf(rmax1, __shfl_xor_sync(0xffffffffu, rmax1, 1));
        rmax1 = fmaxf(rmax1, __shfl_xor_sync(0xffffffffu, rmax1, 2));
        const float mn0 = fmaxf(m0r, rmax0), mn1 = fmaxf(m1r, rmax1);

        float sum0 = 0.f, sum1 = 0.f;
        #pragma unroll
        for (int nt = 0; nt < 8; nt++) {
            float p00 = __expf(s[nt][0] - mn0);
            float p01 = __expf(s[nt][1] - mn0);
            float p10 = __expf(s[nt][2] - mn1);
            float p11 = __expf(s[nt][3] - mn1);
            sum0 += p00 + p01;
            sum1 += p10 + p11;
            float2 v0; v0.x = tf32r(p00); v0.y = tf32r(p01);
            float2 v1; v1.x = tf32r(p10); v1.y = tf32r(p11);
            *(float2*)(Ps + r0 * APITCH + nt * 8 + 2 * q) = v0;
            *(float2*)(Ps + (r0 + 8) * APITCH + nt * 8 + 2 * q) = v1;
        }
        sum0 += __shfl_xor_sync(0xffffffffu, sum0, 1);
        sum0 += __shfl_xor_sync(0xffffffffu, sum0, 2);
        sum1 += __shfl_xor_sync(0xffffffffu, sum1, 1);
        sum1 += __shfl_xor_sync(0xffffffffu, sum1, 2);

        const float c0 = __expf(m0r - mn0), c1 = __expf(m1r - mn1);
        l0r = l0r * c0 + sum0; l1r = l1r * c1 + sum1;
        m0r = mn0; m1r = mn1;
        #pragma unroll
        for (int nt = 0; nt < 8; nt++) {
            o[nt][0] *= c0; o[nt][1] *= c0;
            o[nt][2] *= c1; o[nt][3] *= c1;
        }
        __syncwarp();

        // O += P V   (A = Ps rows [warp's 16], B = Vs[key][d])
        #pragma unroll
        for (int ks = 0; ks < 8; ks++) {
            const int ko = ks * 8;
            uint32_t af[4];
            af[0] = Pu[r0 * APITCH + ko + q];
            af[1] = Pu[(r0 + 8) * APITCH + ko + q];
            af[2] = Pu[r0 * APITCH + ko + q + 4];
            af[3] = Pu[(r0 + 8) * APITCH + ko + q + 4];
            #pragma unroll
            for (int nt = 0; nt < 8; nt++) {
                uint32_t bf[2];
                bf[0] = Vu[(ko + q) * APITCH + nt * 8 + g];
                bf[1] = Vu[(ko + q + 4) * APITCH + nt * 8 + g];
                mma_tf32(o[nt], af, bf);
            }
        }
    }

    // Normalize and write z in [B,H,S,Dh]
    const float inv0 = 1.0f / l0r, inv1 = 1.0f / l1r;
    #pragma unroll
    for (int nt = 0; nt < 8; nt++) {
        const int d = nt * 8 + 2 * q;
        float2 v0; v0.x = o[nt][0] * inv0; v0.y = o[nt][1] * inv0;
        float2 v1; v1.x = o[nt][2] * inv1; v1.y = o[nt][3] * inv1;
        *(float2*)(g_z + base + (size_t)(row0 + r0) * Dd + d) = v0;
        *(float2*)(g_z + base + (size_t)(row0 + r0 + 8) * Dd + d) = v1;
    }
}

// ---------------------------------------------------------------------------
extern "C" void kernel_launch(void* const* d_in, const int* in_sizes, int n_in,
                              void* d_out, int out_size)
{
    const float* x  = (const float*)d_in[0];
    const float* Wq = (const float*)d_in[1];
    const float* bq = (const float*)d_in[2];
    const float* Wk = (const float*)d_in[3];
    const float* bk = (const float*)d_in[4];
    const float* Wv = (const float*)d_in[5];
    const float* bv = (const float*)d_in[6];
    const float* Wo = (const float*)d_in[7];
    const float* bo = (const float*)d_in[8];
    float* out = (float*)d_out;

    cudaFuncSetAttribute(proj_mma,
                         cudaFuncAttributeMaxDynamicSharedMemorySize, GEMM_SMEM);
    cudaFuncSetAttribute(outproj_mma,
                         cudaFuncAttributeMaxDynamicSharedMemorySize, GEMM_SMEM);
    cudaFuncSetAttribute(attn_mma,
                         cudaFuncAttributeMaxDynamicSharedMemorySize, ATTN_SMEM);

    proj_mma<<<dim3(Nn/128, Mm/128, 3), 256, GEMM_SMEM>>>(x, Wq, bq, Wk, bk, Wv, bv);
    attn_mma<<<dim3(Ss/64, Bb*Hh), 128, ATTN_SMEM>>>();
    outproj_mma<<<dim3(Ee/128, Mm/128), 256, GEMM_SMEM>>>(Wo, bo, out);
}

// round 4
// speedup vs baseline: 3.2700x; 1.4176x over previous
#include <cuda_runtime.h>
#include <cstdint>
#include <math.h>

// Problem constants
#define Bb 4
#define Ss 2048
#define Ee 1024
#define Hh 16
#define Dd 64
#define Mm (Bb*Ss)      // 8192
#define Nn (Hh*Dd)      // 1024

// Scratch (device globals: allocation-free, graph-capture safe)
__device__ float g_q[(size_t)Bb*Hh*Ss*Dd];
__device__ float g_k[(size_t)Bb*Hh*Ss*Dd];
__device__ float g_v[(size_t)Bb*Hh*Ss*Dd];
__device__ float g_z[(size_t)Bb*Hh*Ss*Dd];
// tf32-prerounded operands
__device__ float g_xr[(size_t)Mm*Ee];
__device__ float g_wqr[(size_t)Hh*Ee*Dd];
__device__ float g_wkr[(size_t)Hh*Ee*Dd];
__device__ float g_wvr[(size_t)Hh*Ee*Dd];
__device__ float g_wor[(size_t)Nn*Ee];

// ---------------------------------------------------------------------------
// Helpers
// ---------------------------------------------------------------------------
__device__ __forceinline__ float tf32r(float x) {
    float y; asm("cvt.rna.tf32.f32 %0, %1;" : "=f"(y) : "f"(x)); return y;
}
__device__ __forceinline__ float4 cvt4(float4 v) {
    v.x = tf32r(v.x); v.y = tf32r(v.y); v.z = tf32r(v.z); v.w = tf32r(v.w);
    return v;
}
__device__ __forceinline__ void mma_tf32(float* d, const uint32_t* a,
                                         const uint32_t* b) {
    asm volatile(
        "mma.sync.aligned.m16n8k8.row.col.f32.tf32.tf32.f32 "
        "{%0,%1,%2,%3}, {%4,%5,%6,%7}, {%8,%9}, {%0,%1,%2,%3};"
        : "+f"(d[0]), "+f"(d[1]), "+f"(d[2]), "+f"(d[3])
        : "r"(a[0]), "r"(a[1]), "r"(a[2]), "r"(a[3]), "r"(b[0]), "r"(b[1]));
}
__device__ __forceinline__ uint32_t smem_u32(const void* p) {
    uint32_t a;
    asm("{ .reg .u64 t; cvta.to.shared.u64 t, %1; cvt.u32.u64 %0, t; }"
        : "=r"(a) : "l"(p));
    return a;
}
__device__ __forceinline__ void cpa(uint32_t dst, const void* src) {
    asm volatile("cp.async.cg.shared.global [%0], [%1], 16;"
                 :: "r"(dst), "l"(src));
}
__device__ __forceinline__ void cp_commit() {
    asm volatile("cp.async.commit_group;");
}
template<int N> __device__ __forceinline__ void cp_wait() {
    asm volatile("cp.async.wait_group %0;" :: "n"(N));
}

// ---------------------------------------------------------------------------
// Pre-round pass: tf32-round fp32 arrays (float4 grid-stride)
// ---------------------------------------------------------------------------
__global__ __launch_bounds__(256)
void round_copy(const float4* __restrict__ src, float4* __restrict__ dst, int n4)
{
    int i = blockIdx.x * 256 + threadIdx.x;
    if (i < n4) dst[i] = cvt4(src[i]);
}

// ---------------------------------------------------------------------------
// GEMM config: 128x128 block tile, KC=32, 8 warps (warp tile 64x32),
// 3-stage cp.async pipeline. A smem [128][36] (row-major m,k);
// B smem [32][132] (row-major k,n).
// ---------------------------------------------------------------------------
#define KC 32
#define AP 36
#define BP 132
#define ABYTES (128*AP*4)          // 18432
#define BBYTES (KC*BP*4)           // 16896
#define STG (ABYTES+BBYTES)        // 35328
#define GEMM_SMEM (3*STG)          // 105984

// ---------------------------------------------------------------------------
// Kernel 1: QKV projection.  D[m][n] = sum_e x[m][e]*W[h][e][d], n=h*64+d
// Writes rounded q/k/v in [B,H,S,Dh] layout with bias.
// ---------------------------------------------------------------------------
__global__ __launch_bounds__(256, 2)
void proj_mma(const float* __restrict__ bq, const float* __restrict__ bk,
              const float* __restrict__ bv)
{
    extern __shared__ float sm[];
    const uint32_t sb = smem_u32(sm);
    const int sel = blockIdx.z;
    const float* W    = sel == 0 ? g_wqr : (sel == 1 ? g_wkr : g_wvr);
    const float* bias = sel == 0 ? bq    : (sel == 1 ? bk    : bv);
    float* out        = sel == 0 ? g_q   : (sel == 1 ? g_k   : g_v);

    const int t = threadIdx.x, lane = t & 31, wid = t >> 5;
    const int q = lane & 3, g = lane >> 2;
    const int wm = (wid & 1) * 64, wn = (wid >> 1) * 32;
    const int n0 = blockIdx.x * 128, m0 = blockIdx.y * 128;

    float acc[4][4][4];
    #pragma unroll
    for (int i = 0; i < 4; i++)
        #pragma unroll
        for (int j = 0; j < 4; j++)
            #pragma unroll
            for (int kk = 0; kk < 4; kk++) acc[i][j][kk] = 0.f;

    auto issue = [&](int k0, int s) {
        const uint32_t Ab = sb + s * STG;
        const uint32_t Bbse = Ab + ABYTES;
        #pragma unroll
        for (int j = 0; j < 4; j++) {
            const int idx = t + 256 * j;
            const int row = idx >> 3, k4 = (idx & 7) * 4;
            cpa(Ab + (row * AP + k4) * 4,
                g_xr + (size_t)(m0 + row) * Ee + k0 + k4);
            const int kk = idx >> 5, n4 = (idx & 31) * 4;
            const int ng = n0 + n4;
            cpa(Bbse + (kk * BP + n4) * 4,
                W + (size_t)(ng >> 6) * (Ee * Dd) + (size_t)(k0 + kk) * Dd + (ng & 63));
        }
        cp_commit();
    };
    auto compute = [&](int s) {
        const uint32_t* A = (const uint32_t*)(sm + s * (STG / 4));
        const uint32_t* B = A + ABYTES / 4;
        #pragma unroll
        for (int ks = 0; ks < 4; ks++) {
            const int ko = ks * 8;
            uint32_t af[4][4];
            #pragma unroll
            for (int mt = 0; mt < 4; mt++) {
                const int r = wm + mt * 16 + g;
                af[mt][0] = A[r * AP + ko + q];
                af[mt][1] = A[(r + 8) * AP + ko + q];
                af[mt][2] = A[r * AP + ko + q + 4];
                af[mt][3] = A[(r + 8) * AP + ko + q + 4];
            }
            #pragma unroll
            for (int nt = 0; nt < 4; nt++) {
                const int n = wn + nt * 8 + g;
                uint32_t bf[2];
                bf[0] = B[(ko + q) * BP + n];
                bf[1] = B[(ko + q + 4) * BP + n];
                #pragma unroll
                for (int mt = 0; mt < 4; mt++)
                    mma_tf32(acc[mt][nt], af[mt], bf);
            }
        }
    };

    const int NC = Ee / KC;       // 32
    issue(0, 0);
    issue(KC, 1);
    for (int c = 0; c < NC; c++) {
        if (c + 1 < NC) cp_wait<1>(); else cp_wait<0>();
        __syncthreads();
        compute(c % 3);
        if (c + 2 < NC) issue((c + 2) * KC, (c + 2) % 3);
        __syncthreads();
    }

    // Epilogue: bias + round + write [B,H,S,Dh]
    #pragma unroll
    for (int mt = 0; mt < 4; mt++) {
        #pragma unroll
        for (int rr = 0; rr < 2; rr++) {
            const int r_g = m0 + wm + mt * 16 + g + rr * 8;
            const int bi = r_g >> 11, s = r_g & 2047;
            #pragma unroll
            for (int nt = 0; nt < 4; nt++) {
                const int n_g = n0 + wn + nt * 8 + 2 * q;
                const int h = n_g >> 6, d = n_g & 63;
                float2 v;
                v.x = tf32r(acc[mt][nt][2*rr + 0] + bias[n_g]);
                v.y = tf32r(acc[mt][nt][2*rr + 1] + bias[n_g + 1]);
                *(float2*)(out + ((size_t)(bi * Hh + h) * Ss + s) * Dd + d) = v;
            }
        }
    }
}

// ---------------------------------------------------------------------------
// Kernel 3: output projection. out[m][e] = sum_k z_c[m][k]*Wo[k][e] + bo
// ---------------------------------------------------------------------------
__global__ __launch_bounds__(256, 2)
void outproj_mma(const float* __restrict__ bo, float* __restrict__ outp)
{
    extern __shared__ float sm[];
    const uint32_t sb = smem_u32(sm);
    const int t = threadIdx.x, lane = t & 31, wid = t >> 5;
    const int q = lane & 3, g = lane >> 2;
    const int wm = (wid & 1) * 64, wn = (wid >> 1) * 32;
    const int e0 = blockIdx.x * 128, m0 = blockIdx.y * 128;

    float acc[4][4][4];
    #pragma unroll
    for (int i = 0; i < 4; i++)
        #pragma unroll
        for (int j = 0; j < 4; j++)
            #pragma unroll
            for (int kk = 0; kk < 4; kk++) acc[i][j][kk] = 0.f;

    auto issue = [&](int k0, int s) {
        const uint32_t Ab = sb + s * STG;
        const uint32_t Bbse = Ab + ABYTES;
        const int h = k0 >> 6, d0 = k0 & 63;
        #pragma unroll
        for (int j = 0; j < 4; j++) {
            const int idx = t + 256 * j;
            const int row = idx >> 3, k4 = (idx & 7) * 4;
            const int mg = m0 + row, bi = mg >> 11, ss = mg & 2047;
            cpa(Ab + (row * AP + k4) * 4,
                g_z + ((size_t)(bi * Hh + h) * Ss + ss) * Dd + d0 + k4);
            const int kk = idx >> 5, n4 = (idx & 31) * 4;
            cpa(Bbse + (kk * BP + n4) * 4,
                g_wor + (size_t)(k0 + kk) * Ee + e0 + n4);
        }
        cp_commit();
    };
    auto compute = [&](int s) {
        const uint32_t* A = (const uint32_t*)(sm + s * (STG / 4));
        const uint32_t* B = A + ABYTES / 4;
        #pragma unroll
        for (int ks = 0; ks < 4; ks++) {
            const int ko = ks * 8;
            uint32_t af[4][4];
            #pragma unroll
            for (int mt = 0; mt < 4; mt++) {
                const int r = wm + mt * 16 + g;
                af[mt][0] = A[r * AP + ko + q];
                af[mt][1] = A[(r + 8) * AP + ko + q];
                af[mt][2] = A[r * AP + ko + q + 4];
                af[mt][3] = A[(r + 8) * AP + ko + q + 4];
            }
            #pragma unroll
            for (int nt = 0; nt < 4; nt++) {
                const int n = wn + nt * 8 + g;
                uint32_t bf[2];
                bf[0] = B[(ko + q) * BP + n];
                bf[1] = B[(ko + q + 4) * BP + n];
                #pragma unroll
                for (int mt = 0; mt < 4; mt++)
                    mma_tf32(acc[mt][nt], af[mt], bf);
            }
        }
    };

    const int NC = Nn / KC;       // 32
    issue(0, 0);
    issue(KC, 1);
    for (int c = 0; c < NC; c++) {
        if (c + 1 < NC) cp_wait<1>(); else cp_wait<0>();
        __syncthreads();
        compute(c % 3);
        if (c + 2 < NC) issue((c + 2) * KC, (c + 2) % 3);
        __syncthreads();
    }

    #pragma unroll
    for (int mt = 0; mt < 4; mt++) {
        #pragma unroll
        for (int rr = 0; rr < 2; rr++) {
            const int r_g = m0 + wm + mt * 16 + g + rr * 8;
            #pragma unroll
            for (int nt = 0; nt < 4; nt++) {
                const int e = e0 + wn + nt * 8 + 2 * q;
                float2 v;
                v.x = acc[mt][nt][2*rr + 0] + bo[e];
                v.y = acc[mt][nt][2*rr + 1] + bo[e + 1];
                *(float2*)(outp + (size_t)r_g * Ee + e) = v;
            }
        }
    }
}

// ---------------------------------------------------------------------------
// Kernel 2: flash attention, tf32 mma, cp.async double-buffered K/V.
// 128 threads (4 warps), 64 q-rows/block; warp w owns rows w*16..w*16+15.
// ---------------------------------------------------------------------------
#define APITCH 68
#define TILE_B (64*APITCH*4)                    // 17408
#define OFF_Q  0
#define OFF_P  TILE_B
#define OFF_K0 (2*TILE_B)
#define OFF_V0 (3*TILE_B)
#define OFF_K1 (4*TILE_B)
#define OFF_V1 (5*TILE_B)
#define ATTN_SMEM (6*TILE_B)                    // 104448

__global__ __launch_bounds__(128, 2)
void attn_mma()
{
    extern __shared__ float sm[];
    const uint32_t sb = smem_u32(sm);
    const uint32_t* Qu = (const uint32_t*)(sm + OFF_Q/4);
    const uint32_t* Pu = (const uint32_t*)(sm + OFF_P/4);
    float* Ps = sm + OFF_P/4;

    const int t = threadIdx.x, lane = t & 31, wid = t >> 5;
    const int q = lane & 3, g = lane >> 2;
    const int bh = blockIdx.y;
    const int row0 = blockIdx.x * 64;
    const size_t base = (size_t)bh * Ss * Dd;
    const int r0 = wid * 16 + g;

    auto issueKV = [&](int t0, int s) {
        const uint32_t Kb = sb + (s ? OFF_K1 : OFF_K0);
        const uint32_t Vb = sb + (s ? OFF_V1 : OFF_V0);
        #pragma unroll
        for (int j = 0; j < 8; j++) {
            const int idx = t + 128 * j;
            const int r = idx >> 4, c4 = (idx & 15) * 4;
            const size_t go = base + (size_t)(t0 + r) * Dd + c4;
            const uint32_t so = (r * APITCH + c4) * 4;
            cpa(Kb + so, g_k + go);
            cpa(Vb + so, g_v + go);
        }
        cp_commit();
    };

    // Prologue: Q + KV tile 0
    {
        #pragma unroll
        for (int j = 0; j < 8; j++) {
            const int idx = t + 128 * j;
            const int r = idx >> 4, c4 = (idx & 15) * 4;
            cpa(sb + OFF_Q + (r * APITCH + c4) * 4,
                g_q + base + (size_t)(row0 + r) * Dd + c4);
        }
        cp_commit();
    }
    issueKV(0, 0);

    float m0r = -3.0e38f, m1r = -3.0e38f, l0r = 0.f, l1r = 0.f;
    float o[8][4];
    #pragma unroll
    for (int i = 0; i < 8; i++)
        #pragma unroll
        for (int j = 0; j < 4; j++) o[i][j] = 0.f;

    const int NT = Ss / 64;   // 32
    for (int it = 0; it < NT; it++) {
        const int buf = it & 1;
        if (it + 1 < NT) issueKV((it + 1) * 64, buf ^ 1);
        if (it + 1 < NT) cp_wait<1>(); else cp_wait<0>();
        __syncthreads();

        const uint32_t* Ku = (const uint32_t*)(sm + (buf ? OFF_K1 : OFF_K0)/4);
        const uint32_t* Vu = (const uint32_t*)(sm + (buf ? OFF_V1 : OFF_V0)/4);

        // S = Q K^T
        float s[8][4];
        #pragma unroll
        for (int i = 0; i < 8; i++)
            #pragma unroll
            for (int j = 0; j < 4; j++) s[i][j] = 0.f;
        #pragma unroll
        for (int ks = 0; ks < 8; ks++) {
            const int ko = ks * 8;
            uint32_t af[4];
            af[0] = Qu[r0 * APITCH + ko + q];
            af[1] = Qu[(r0 + 8) * APITCH + ko + q];
            af[2] = Qu[r0 * APITCH + ko + q + 4];
            af[3] = Qu[(r0 + 8) * APITCH + ko + q + 4];
            #pragma unroll
            for (int nt = 0; nt < 8; nt++) {
                const int n = nt * 8 + g;
                uint32_t bf[2];
                bf[0] = Ku[n * APITCH + ko + q];
                bf[1] = Ku[n * APITCH + ko + q + 4];
                mma_tf32(s[nt], af, bf);
            }
        }

        // Online softmax (rows r0 -> s[..][0,1]; r0+8 -> s[..][2,3])
        float rmax0 = -3.0e38f, rmax1 = -3.0e38f;
        #pragma unroll
        for (int nt = 0; nt < 8; nt++) {
            #pragma unroll
            for (int j = 0; j < 4; j++) s[nt][j] *= 0.125f;
            rmax0 = fmaxf(rmax0, fmaxf(s[nt][0], s[nt][1]));
            rmax1 = fmaxf(rmax1, fmaxf(s[nt][2], s[nt][3]));
        }
        rmax0 = fmaxf(rmax0, __shfl_xor_sync(0xffffffffu, rmax0, 1));
        rmax0 = fmaxf(rmax0, __shfl_xor_sync(0xffffffffu, rmax0, 2));
        rmax1 = fmaxf(rmax1, __shfl_xor_sync(0xffffffffu, rmax1, 1));
        rmax1 = fmaxf(rmax1, __shfl_xor_sync(0xffffffffu, rmax1, 2));
        const float mn0 = fmaxf(m0r, rmax0), mn1 = fmaxf(m1r, rmax1);

        float sum0 = 0.f, sum1 = 0.f;
        #pragma unroll
        for (int nt = 0; nt < 8; nt++) {
            float p00 = __expf(s[nt][0] - mn0);
            float p01 = __expf(s[nt][1] - mn0);
            float p10 = __expf(s[nt][2] - mn1);
            float p11 = __expf(s[nt][3] - mn1);
            sum0 += p00 + p01;
            sum1 += p10 + p11;
            float2 v0; v0.x = tf32r(p00); v0.y = tf32r(p01);
            float2 v1; v1.x = tf32r(p10); v1.y = tf32r(p11);
            *(float2*)(Ps + r0 * APITCH + nt * 8 + 2 * q) = v0;
            *(float2*)(Ps + (r0 + 8) * APITCH + nt * 8 + 2 * q) = v1;
        }
        sum0 += __shfl_xor_sync(0xffffffffu, sum0, 1);
        sum0 += __shfl_xor_sync(0xffffffffu, sum0, 2);
        sum1 += __shfl_xor_sync(0xffffffffu, sum1, 1);
        sum1 += __shfl_xor_sync(0xffffffffu, sum1, 2);

        const float c0 = __expf(m0r - mn0), c1 = __expf(m1r - mn1);
        l0r = l0r * c0 + sum0; l1r = l1r * c1 + sum1;
        m0r = mn0; m1r = mn1;
        #pragma unroll
        for (int nt = 0; nt < 8; nt++) {
            o[nt][0] *= c0; o[nt][1] *= c0;
            o[nt][2] *= c1; o[nt][3] *= c1;
        }
        __syncwarp();

        // O += P V
        #pragma unroll
        for (int ks = 0; ks < 8; ks++) {
            const int ko = ks * 8;
            uint32_t af[4];
            af[0] = Pu[r0 * APITCH + ko + q];
            af[1] = Pu[(r0 + 8) * APITCH + ko + q];
            af[2] = Pu[r0 * APITCH + ko + q + 4];
            af[3] = Pu[(r0 + 8) * APITCH + ko + q + 4];
            #pragma unroll
            for (int nt = 0; nt < 8; nt++) {
                uint32_t bf[2];
                bf[0] = Vu[(ko + q) * APITCH + nt * 8 + g];
                bf[1] = Vu[(ko + q + 4) * APITCH + nt * 8 + g];
                mma_tf32(o[nt], af, bf);
            }
        }
        __syncthreads();   // all warps done with buf before it is refilled
    }

    // Normalize, round, write z in [B,H,S,Dh]
    const float inv0 = 1.0f / l0r, inv1 = 1.0f / l1r;
    #pragma unroll
    for (int nt = 0; nt < 8; nt++) {
        const int d = nt * 8 + 2 * q;
        float2 v0; v0.x = tf32r(o[nt][0] * inv0); v0.y = tf32r(o[nt][1] * inv0);
        float2 v1; v1.x = tf32r(o[nt][2] * inv1); v1.y = tf32r(o[nt][3] * inv1);
        *(float2*)(g_z + base + (size_t)(row0 + r0) * Dd + d) = v0;
        *(float2*)(g_z + base + (size_t)(row0 + r0 + 8) * Dd + d) = v1;
    }
}

// ---------------------------------------------------------------------------
extern "C" void kernel_launch(void* const* d_in, const int* in_sizes, int n_in,
                              void* d_out, int out_size)
{
    const float* x  = (const float*)d_in[0];
    const float* Wq = (const float*)d_in[1];
    const float* bq = (const float*)d_in[2];
    const float* Wk = (const float*)d_in[3];
    const float* bk = (const float*)d_in[4];
    const float* Wv = (const float*)d_in[5];
    const float* bv = (const float*)d_in[6];
    const float* Wo = (const float*)d_in[7];
    const float* bo = (const float*)d_in[8];
    float* out = (float*)d_out;

    cudaFuncSetAttribute(proj_mma,
                         cudaFuncAttributeMaxDynamicSharedMemorySize, GEMM_SMEM);
    cudaFuncSetAttribute(outproj_mma,
                         cudaFuncAttributeMaxDynamicSharedMemorySize, GEMM_SMEM);
    cudaFuncSetAttribute(attn_mma,
                         cudaFuncAttributeMaxDynamicSharedMemorySize, ATTN_SMEM);

    // Resolve device-global addresses host-side
    float *xr, *wqr, *wkr, *wvr, *wor;
    cudaGetSymbolAddress((void**)&xr,  g_xr);
    cudaGetSymbolAddress((void**)&wqr, g_wqr);
    cudaGetSymbolAddress((void**)&wkr, g_wkr);
    cudaGetSymbolAddress((void**)&wvr, g_wvr);
    cudaGetSymbolAddress((void**)&wor, g_wor);

    const int nx4 = Mm * Ee / 4;           // 2097152
    const int nw4 = Hh * Ee * Dd / 4;      // 262144
    round_copy<<<(nx4 + 255)/256, 256>>>((const float4*)x,  (float4*)xr,  nx4);
    round_copy<<<(nw4 + 255)/256, 256>>>((const float4*)Wq, (float4*)wqr, nw4);
    round_copy<<<(nw4 + 255)/256, 256>>>((const float4*)Wk, (float4*)wkr, nw4);
    round_copy<<<(nw4 + 255)/256, 256>>>((const float4*)Wv, (float4*)wvr, nw4);
    round_copy<<<(nw4 + 255)/256, 256>>>((const float4*)Wo, (float4*)wor, nw4);

    proj_mma<<<dim3(Nn/128, Mm/128, 3), 256, GEMM_SMEM>>>(bq, bk, bv);
    attn_mma<<<dim3(Ss/64, Bb*Hh), 128, ATTN_SMEM>>>();
    outproj_mma<<<dim3(Ee/128, Mm/128), 256, GEMM_SMEM>>>(bo, out);
}

// round 5
// speedup vs baseline: 3.6057x; 1.1026x over previous
#include <cuda_runtime.h>
#include <cstdint>
#include <math.h>

// Problem constants
#define Bb 4
#define Ss 2048
#define Ee 1024
#define Hh 16
#define Dd 64
#define Mm (Bb*Ss)      // 8192
#define Nn (Hh*Dd)      // 1024

// q scale folded with log2(e): exp(s*0.125) = 2^(s*0.125*log2e)
#define QSCL 0.18033688011112042f

// Scratch (device globals: allocation-free, graph-capture safe)
__device__ float g_q[(size_t)Bb*Hh*Ss*Dd];   // [b,h,s,d], pre-scaled by QSCL
__device__ float g_k[(size_t)Bb*Hh*Ss*Dd];   // [b,h,s,d]
__device__ float g_v[(size_t)Bb*Hh*Ss*Dd];   // [b,h,d,s]  (TRANSPOSED)
__device__ float g_z[(size_t)Bb*Hh*Ss*Dd];   // [b,h,s,d]
// tf32-prerounded operands
__device__ float g_xr[(size_t)Mm*Ee];
__device__ float g_wqr[(size_t)Hh*Ee*Dd];
__device__ float g_wkr[(size_t)Hh*Ee*Dd];
__device__ float g_wvr[(size_t)Hh*Ee*Dd];
__device__ float g_wor[(size_t)Nn*Ee];

// ---------------------------------------------------------------------------
// Helpers
// ---------------------------------------------------------------------------
__device__ __forceinline__ float tf32r(float x) {
    float y; asm("cvt.rna.tf32.f32 %0, %1;" : "=f"(y) : "f"(x)); return y;
}
__device__ __forceinline__ float ex2(float x) {
    float y; asm("ex2.approx.f32 %0, %1;" : "=f"(y) : "f"(x)); return y;
}
__device__ __forceinline__ float4 cvt4(float4 v) {
    v.x = tf32r(v.x); v.y = tf32r(v.y); v.z = tf32r(v.z); v.w = tf32r(v.w);
    return v;
}
__device__ __forceinline__ void mma_tf32(float* d, const uint32_t* a,
                                         const uint32_t* b) {
    asm volatile(
        "mma.sync.aligned.m16n8k8.row.col.f32.tf32.tf32.f32 "
        "{%0,%1,%2,%3}, {%4,%5,%6,%7}, {%8,%9}, {%0,%1,%2,%3};"
        : "+f"(d[0]), "+f"(d[1]), "+f"(d[2]), "+f"(d[3])
        : "r"(a[0]), "r"(a[1]), "r"(a[2]), "r"(a[3]), "r"(b[0]), "r"(b[1]));
}
__device__ __forceinline__ uint32_t smem_u32(const void* p) {
    uint32_t a;
    asm("{ .reg .u64 t; cvta.to.shared.u64 t, %1; cvt.u32.u64 %0, t; }"
        : "=r"(a) : "l"(p));
    return a;
}
__device__ __forceinline__ void cpa(uint32_t dst, const void* src) {
    asm volatile("cp.async.cg.shared.global [%0], [%1], 16;"
                 :: "r"(dst), "l"(src));
}
__device__ __forceinline__ void cp_commit() {
    asm volatile("cp.async.commit_group;");
}
template<int N> __device__ __forceinline__ void cp_wait() {
    asm volatile("cp.async.wait_group %0;" :: "n"(N));
}

// ---------------------------------------------------------------------------
// Pre-round pass
// ---------------------------------------------------------------------------
__global__ __launch_bounds__(256)
void round_copy(const float4* __restrict__ src, float4* __restrict__ dst, int n4)
{
    int i = blockIdx.x * 256 + threadIdx.x;
    if (i < n4) dst[i] = cvt4(src[i]);
}

// ---------------------------------------------------------------------------
// GEMM config: 128x128 tile, KC=32, 8 warps (warp tile 64x32), 3-stage cp.async
// ---------------------------------------------------------------------------
#define KC 32
#define AP 36
#define BP 132
#define ABYTES (128*AP*4)
#define BBYTES (KC*BP*4)
#define STG (ABYTES+BBYTES)
#define GEMM_SMEM (3*STG)

// ---------------------------------------------------------------------------
// Kernel 1: QKV projection
// ---------------------------------------------------------------------------
__global__ __launch_bounds__(256, 2)
void proj_mma(const float* __restrict__ bq, const float* __restrict__ bk,
              const float* __restrict__ bv)
{
    extern __shared__ float sm[];
    const uint32_t sb = smem_u32(sm);
    const int sel = blockIdx.z;
    const float* W    = sel == 0 ? g_wqr : (sel == 1 ? g_wkr : g_wvr);
    const float* bias = sel == 0 ? bq    : (sel == 1 ? bk    : bv);

    const int t = threadIdx.x, lane = t & 31, wid = t >> 5;
    const int q = lane & 3, g = lane >> 2;
    const int wm = (wid & 1) * 64, wn = (wid >> 1) * 32;
    const int n0 = blockIdx.x * 128, m0 = blockIdx.y * 128;

    float acc[4][4][4];
    #pragma unroll
    for (int i = 0; i < 4; i++)
        #pragma unroll
        for (int j = 0; j < 4; j++)
            #pragma unroll
            for (int kk = 0; kk < 4; kk++) acc[i][j][kk] = 0.f;

    auto issue = [&](int k0, int s) {
        const uint32_t Ab = sb + s * STG;
        const uint32_t Bbse = Ab + ABYTES;
        #pragma unroll
        for (int j = 0; j < 4; j++) {
            const int idx = t + 256 * j;
            const int row = idx >> 3, k4 = (idx & 7) * 4;
            cpa(Ab + (row * AP + k4) * 4,
                g_xr + (size_t)(m0 + row) * Ee + k0 + k4);
            const int kk = idx >> 5, n4 = (idx & 31) * 4;
            const int ng = n0 + n4;
            cpa(Bbse + (kk * BP + n4) * 4,
                W + (size_t)(ng >> 6) * (Ee * Dd) + (size_t)(k0 + kk) * Dd + (ng & 63));
        }
        cp_commit();
    };
    auto compute = [&](int s) {
        const uint32_t* A = (const uint32_t*)(sm + s * (STG / 4));
        const uint32_t* B = A + ABYTES / 4;
        #pragma unroll
        for (int ks = 0; ks < 4; ks++) {
            const int ko = ks * 8;
            uint32_t af[4][4];
            #pragma unroll
            for (int mt = 0; mt < 4; mt++) {
                const int r = wm + mt * 16 + g;
                af[mt][0] = A[r * AP + ko + q];
                af[mt][1] = A[(r + 8) * AP + ko + q];
                af[mt][2] = A[r * AP + ko + q + 4];
                af[mt][3] = A[(r + 8) * AP + ko + q + 4];
            }
            #pragma unroll
            for (int nt = 0; nt < 4; nt++) {
                const int n = wn + nt * 8 + g;
                uint32_t bf[2];
                bf[0] = B[(ko + q) * BP + n];
                bf[1] = B[(ko + q + 4) * BP + n];
                #pragma unroll
                for (int mt = 0; mt < 4; mt++)
                    mma_tf32(acc[mt][nt], af[mt], bf);
            }
        }
    };

    const int NC = Ee / KC;
    issue(0, 0);
    issue(KC, 1);
    for (int c = 0; c < NC; c++) {
        if (c + 1 < NC) cp_wait<1>(); else cp_wait<0>();
        __syncthreads();
        if (c + 2 < NC) issue((c + 2) * KC, (c + 2) % 3);
        compute(c % 3);
    }

    // Epilogue
    #pragma unroll
    for (int mt = 0; mt < 4; mt++) {
        #pragma unroll
        for (int rr = 0; rr < 2; rr++) {
            const int r_g = m0 + wm + mt * 16 + g + rr * 8;
            const int bi = r_g >> 11, s = r_g & 2047;
            #pragma unroll
            for (int nt = 0; nt < 4; nt++) {
                const int n_g = n0 + wn + nt * 8 + 2 * q;
                const int h = n_g >> 6, d = n_g & 63;
                float vx = acc[mt][nt][2*rr + 0] + bias[n_g];
                float vy = acc[mt][nt][2*rr + 1] + bias[n_g + 1];
                if (sel == 0) {
                    float2 v;
                    v.x = tf32r(vx * QSCL);
                    v.y = tf32r(vy * QSCL);
                    *(float2*)(g_q + ((size_t)(bi * Hh + h) * Ss + s) * Dd + d) = v;
                } else if (sel == 1) {
                    float2 v;
                    v.x = tf32r(vx); v.y = tf32r(vy);
                    *(float2*)(g_k + ((size_t)(bi * Hh + h) * Ss + s) * Dd + d) = v;
                } else {
                    // V transposed: [b,h,d,s]
                    const size_t vb = ((size_t)(bi * Hh + h) * Dd);
                    g_v[(vb + d)     * Ss + s] = tf32r(vx);
                    g_v[(vb + d + 1) * Ss + s] = tf32r(vy);
                }
            }
        }
    }
}

// ---------------------------------------------------------------------------
// Kernel 3: output projection
// ---------------------------------------------------------------------------
__global__ __launch_bounds__(256, 2)
void outproj_mma(const float* __restrict__ bo, float* __restrict__ outp)
{
    extern __shared__ float sm[];
    const uint32_t sb = smem_u32(sm);
    const int t = threadIdx.x, lane = t & 31, wid = t >> 5;
    const int q = lane & 3, g = lane >> 2;
    const int wm = (wid & 1) * 64, wn = (wid >> 1) * 32;
    const int e0 = blockIdx.x * 128, m0 = blockIdx.y * 128;

    float acc[4][4][4];
    #pragma unroll
    for (int i = 0; i < 4; i++)
        #pragma unroll
        for (int j = 0; j < 4; j++)
            #pragma unroll
            for (int kk = 0; kk < 4; kk++) acc[i][j][kk] = 0.f;

    auto issue = [&](int k0, int s) {
        const uint32_t Ab = sb + s * STG;
        const uint32_t Bbse = Ab + ABYTES;
        const int h = k0 >> 6, d0 = k0 & 63;
        #pragma unroll
        for (int j = 0; j < 4; j++) {
            const int idx = t + 256 * j;
            const int row = idx >> 3, k4 = (idx & 7) * 4;
            const int mg = m0 + row, bi = mg >> 11, ss = mg & 2047;
            cpa(Ab + (row * AP + k4) * 4,
                g_z + ((size_t)(bi * Hh + h) * Ss + ss) * Dd + d0 + k4);
            const int kk = idx >> 5, n4 = (idx & 31) * 4;
            cpa(Bbse + (kk * BP + n4) * 4,
                g_wor + (size_t)(k0 + kk) * Ee + e0 + n4);
        }
        cp_commit();
    };
    auto compute = [&](int s) {
        const uint32_t* A = (const uint32_t*)(sm + s * (STG / 4));
        const uint32_t* B = A + ABYTES / 4;
        #pragma unroll
        for (int ks = 0; ks < 4; ks++) {
            const int ko = ks * 8;
            uint32_t af[4][4];
            #pragma unroll
            for (int mt = 0; mt < 4; mt++) {
                const int r = wm + mt * 16 + g;
                af[mt][0] = A[r * AP + ko + q];
                af[mt][1] = A[(r + 8) * AP + ko + q];
                af[mt][2] = A[r * AP + ko + q + 4];
                af[mt][3] = A[(r + 8) * AP + ko + q + 4];
            }
            #pragma unroll
            for (int nt = 0; nt < 4; nt++) {
                const int n = wn + nt * 8 + g;
                uint32_t bf[2];
                bf[0] = B[(ko + q) * BP + n];
                bf[1] = B[(ko + q + 4) * BP + n];
                #pragma unroll
                for (int mt = 0; mt < 4; mt++)
                    mma_tf32(acc[mt][nt], af[mt], bf);
            }
        }
    };

    const int NC = Nn / KC;
    issue(0, 0);
    issue(KC, 1);
    for (int c = 0; c < NC; c++) {
        if (c + 1 < NC) cp_wait<1>(); else cp_wait<0>();
        __syncthreads();
        if (c + 2 < NC) issue((c + 2) * KC, (c + 2) % 3);
        compute(c % 3);
    }

    #pragma unroll
    for (int mt = 0; mt < 4; mt++) {
        #pragma unroll
        for (int rr = 0; rr < 2; rr++) {
            const int r_g = m0 + wm + mt * 16 + g + rr * 8;
            #pragma unroll
            for (int nt = 0; nt < 4; nt++) {
                const int e = e0 + wn + nt * 8 + 2 * q;
                float2 v;
                v.x = acc[mt][nt][2*rr + 0] + bo[e];
                v.y = acc[mt][nt][2*rr + 1] + bo[e + 1];
                *(float2*)(outp + (size_t)r_g * Ee + e) = v;
            }
        }
    }
}

// ---------------------------------------------------------------------------
// Kernel 2: flash attention. 256 threads (8 warps), 256 q-rows/block,
// warp owns 32 rows (2 m16 tiles); 64-key tiles, double-buffered K/V.
// Q pre-scaled by 0.125*log2e -> softmax in log2 domain via ex2.
// ---------------------------------------------------------------------------
#define APITCH 68
#define AROWS 256
#define QF (AROWS*APITCH)
#define KVF (64*APITCH)
#define FO_Q  0
#define FO_P  QF
#define FO_K0 (2*QF)
#define FO_V0 (2*QF + KVF)
#define FO_K1 (2*QF + 2*KVF)
#define FO_V1 (2*QF + 3*KVF)
#define ATTN_SMEM ((2*QF + 4*KVF)*4)     // 208896

__global__ __launch_bounds__(256)
void attn_mma()
{
    extern __shared__ float sm[];
    const uint32_t sb = smem_u32(sm);
    const int t = threadIdx.x, lane = t & 31, wid = t >> 5;
    const int q = lane & 3, g = lane >> 2;
    const int bh = blockIdx.y;
    const int row0 = blockIdx.x * AROWS;
    const size_t baseq = (size_t)bh * Ss * Dd;   // q,k: [s][d]
    const size_t basev = (size_t)bh * Dd * Ss;   // v:   [d][s]
    const int wr = wid * 32;

    const uint32_t* Qu = (const uint32_t*)sm + FO_Q;
    uint32_t* Pu = (uint32_t*)sm + FO_P;
    float* Ps = sm + FO_P;

    auto issueKV = [&](int t0, int s) {
        const uint32_t Kb = sb + (s ? FO_K1 : FO_K0) * 4;
        const uint32_t Vb = sb + (s ? FO_V1 : FO_V0) * 4;
        #pragma unroll
        for (int j = 0; j < 4; j++) {
            const int idx = t + 256 * j;
            const int r = idx >> 4, c4 = (idx & 15) * 4;
            cpa(Kb + (r * APITCH + c4) * 4, g_k + baseq + (size_t)(t0 + r) * Dd + c4);
            cpa(Vb + (r * APITCH + c4) * 4, g_v + basev + (size_t)r * Ss + t0 + c4);
        }
        cp_commit();
    };

    // Prologue: Q + KV tile 0, single group
    #pragma unroll
    for (int j = 0; j < 16; j++) {
        const int idx = t + 256 * j;
        const int r = idx >> 4, c4 = (idx & 15) * 4;
        cpa(sb + (FO_Q + r * APITCH + c4) * 4,
            g_q + baseq + (size_t)(row0 + r) * Dd + c4);
    }
    #pragma unroll
    for (int j = 0; j < 4; j++) {
        const int idx = t + 256 * j;
        const int r = idx >> 4, c4 = (idx & 15) * 4;
        cpa(sb + (FO_K0 + r * APITCH + c4) * 4, g_k + baseq + (size_t)r * Dd + c4);
        cpa(sb + (FO_V0 + r * APITCH + c4) * 4, g_v + basev + (size_t)r * Ss + c4);
    }
    cp_commit();

    float mR[4], lR[4], o[2][8][4];
    #pragma unroll
    for (int i = 0; i < 4; i++) { mR[i] = -3.0e38f; lR[i] = 0.f; }
    #pragma unroll
    for (int mt = 0; mt < 2; mt++)
        #pragma unroll
        for (int nt = 0; nt < 8; nt++)
            #pragma unroll
            for (int c = 0; c < 4; c++) o[mt][nt][c] = 0.f;

    const int NT = Ss / 64;
    for (int it = 0; it < NT; it++) {
        cp_wait<0>();
        __syncthreads();
        const int buf = it & 1;
        if (it + 1 < NT) issueKV((it + 1) * 64, buf ^ 1);

        const uint32_t* Ku = (const uint32_t*)sm + (buf ? FO_K1 : FO_K0);
        const uint32_t* Vu = (const uint32_t*)sm + (buf ? FO_V1 : FO_V0);

        // S = Q K^T  (log2-domain scores, scale pre-folded into Q)
        float s[2][8][4];
        #pragma unroll
        for (int mt = 0; mt < 2; mt++)
            #pragma unroll
            for (int nt = 0; nt < 8; nt++)
                #pragma unroll
                for (int c = 0; c < 4; c++) s[mt][nt][c] = 0.f;
        #pragma unroll
        for (int ks = 0; ks < 8; ks++) {
            const int ko = ks * 8;
            uint32_t af[2][4];
            #pragma unroll
            for (int mt = 0; mt < 2; mt++) {
                const int r = wr + mt * 16 + g;
                af[mt][0] = Qu[r * APITCH + ko + q];
                af[mt][1] = Qu[(r + 8) * APITCH + ko + q];
                af[mt][2] = Qu[r * APITCH + ko + q + 4];
                af[mt][3] = Qu[(r + 8) * APITCH + ko + q + 4];
            }
            #pragma unroll
            for (int nt = 0; nt < 8; nt++) {
                uint32_t bf[2];
                bf[0] = Ku[(nt * 8 + g) * APITCH + ko + q];
                bf[1] = Ku[(nt * 8 + g) * APITCH + ko + q + 4];
                #pragma unroll
                for (int mt = 0; mt < 2; mt++)
                    mma_tf32(s[mt][nt], af[mt], bf);
            }
        }

        // Online softmax (log2 domain). Row instance ri = mt*2+rr.
        #pragma unroll
        for (int mt = 0; mt < 2; mt++) {
            #pragma unroll
            for (int rr = 0; rr < 2; rr++) {
                const int ri = mt * 2 + rr;
                float rmax = -3.0e38f;
                #pragma unroll
                for (int nt = 0; nt < 8; nt++)
                    rmax = fmaxf(rmax, fmaxf(s[mt][nt][2*rr], s[mt][nt][2*rr+1]));
                rmax = fmaxf(rmax, __shfl_xor_sync(0xffffffffu, rmax, 1));
                rmax = fmaxf(rmax, __shfl_xor_sync(0xffffffffu, rmax, 2));
                const float mn = fmaxf(mR[ri], rmax);
                float sum = 0.f;
                const int prow = wr + mt * 16 + rr * 8 + g;
                #pragma unroll
                for (int nt = 0; nt < 8; nt++) {
                    float p0 = ex2(s[mt][nt][2*rr]   - mn);
                    float p1 = ex2(s[mt][nt][2*rr+1] - mn);
                    sum += p0 + p1;
                    float2 v; v.x = tf32r(p0); v.y = tf32r(p1);
                    *(float2*)(Ps + prow * APITCH + nt * 8 + 2 * q) = v;
                }
                sum += __shfl_xor_sync(0xffffffffu, sum, 1);
                sum += __shfl_xor_sync(0xffffffffu, sum, 2);
                const float corr = ex2(mR[ri] - mn);
                lR[ri] = lR[ri] * corr + sum;
                mR[ri] = mn;
                #pragma unroll
                for (int nt = 0; nt < 8; nt++) {
                    o[mt][nt][2*rr]   *= corr;
                    o[mt][nt][2*rr+1] *= corr;
                }
            }
        }
        __syncwarp();

        // O += P V
        #pragma unroll
        for (int ks = 0; ks < 8; ks++) {
            const int ko = ks * 8;
            uint32_t af[2][4];
            #pragma unroll
            for (int mt = 0; mt < 2; mt++) {
                const int r = wr + mt * 16 + g;
                af[mt][0] = Pu[r * APITCH + ko + q];
                af[mt][1] = Pu[(r + 8) * APITCH + ko + q];
                af[mt][2] = Pu[r * APITCH + ko + q + 4];
                af[mt][3] = Pu[(r + 8) * APITCH + ko + q + 4];
            }
            #pragma unroll
            for (int nt = 0; nt < 8; nt++) {
                uint32_t bf[2];
                bf[0] = Vu[(nt * 8 + g) * APITCH + ko + q];
                bf[1] = Vu[(nt * 8 + g) * APITCH + ko + q + 4];
                #pragma unroll
                for (int mt = 0; mt < 2; mt++)
                    mma_tf32(o[mt][nt], af[mt], bf);
            }
        }
    }

    // Normalize, round, write z [B,H,S,Dh]
    #pragma unroll
    for (int mt = 0; mt < 2; mt++) {
        #pragma unroll
        for (int rr = 0; rr < 2; rr++) {
            const float inv = 1.0f / lR[mt * 2 + rr];
            const int r_g = row0 + wr + mt * 16 + rr * 8 + g;
            #pragma unroll
            for (int nt = 0; nt < 8; nt++) {
                const int d = nt * 8 + 2 * q;
                float2 v;
                v.x = tf32r(o[mt][nt][2*rr]   * inv);
                v.y = tf32r(o[mt][nt][2*rr+1] * inv);
                *(float2*)(g_z + baseq + (size_t)r_g * Dd + d) = v;
            }
        }
    }
}

// ---------------------------------------------------------------------------
extern "C" void kernel_launch(void* const* d_in, const int* in_sizes, int n_in,
                              void* d_out, int out_size)
{
    const float* x  = (const float*)d_in[0];
    const float* Wq = (const float*)d_in[1];
    const float* bq = (const float*)d_in[2];
    const float* Wk = (const float*)d_in[3];
    const float* bk = (const float*)d_in[4];
    const float* Wv = (const float*)d_in[5];
    const float* bv = (const float*)d_in[6];
    const float* Wo = (const float*)d_in[7];
    const float* bo = (const float*)d_in[8];
    float* out = (float*)d_out;

    cudaFuncSetAttribute(proj_mma,
                         cudaFuncAttributeMaxDynamicSharedMemorySize, GEMM_SMEM);
    cudaFuncSetAttribute(outproj_mma,
                         cudaFuncAttributeMaxDynamicSharedMemorySize, GEMM_SMEM);
    cudaFuncSetAttribute(attn_mma,
                         cudaFuncAttributeMaxDynamicSharedMemorySize, ATTN_SMEM);

    float *xr, *wqr, *wkr, *wvr, *wor;
    cudaGetSymbolAddress((void**)&xr,  g_xr);
    cudaGetSymbolAddress((void**)&wqr, g_wqr);
    cudaGetSymbolAddress((void**)&wkr, g_wkr);
    cudaGetSymbolAddress((void**)&wvr, g_wvr);
    cudaGetSymbolAddress((void**)&wor, g_wor);

    const int nx4 = Mm * Ee / 4;
    const int nw4 = Hh * Ee * Dd / 4;
    round_copy<<<(nx4 + 255)/256, 256>>>((const float4*)x,  (float4*)xr,  nx4);
    round_copy<<<(nw4 + 255)/256, 256>>>((const float4*)Wq, (float4*)wqr, nw4);
    round_copy<<<(nw4 + 255)/256, 256>>>((const float4*)Wk, (float4*)wkr, nw4);
    round_copy<<<(nw4 + 255)/256, 256>>>((const float4*)Wv, (float4*)wvr, nw4);
    round_copy<<<(nw4 + 255)/256, 256>>>((const float4*)Wo, (float4*)wor, nw4);

    proj_mma<<<dim3(Nn/128, Mm/128, 3), 256, GEMM_SMEM>>>(bq, bk, bv);
    attn_mma<<<dim3(Ss/AROWS, Bb*Hh), 256, ATTN_SMEM>>>();
    outproj_mma<<<dim3(Ee/128, Mm/128), 256, GEMM_SMEM>>>(bo, out);
}